// round 4
// baseline (speedup 1.0000x reference)
#include <cuda_runtime.h>
#include <math.h>
#include <stdint.h>

// Problem constants
#define BB    2
#define SEQ   4096
#define NH    16
#define HD    128
#define HIDN  2048
#define CHK   128
#define NC    32
#define NROWS (BB*SEQ)      // 8192
#define FEPS  1e-6f

// ---------------- scratch (device globals; no runtime allocation allowed) ----
static __device__ float g_qf [NROWS*HIDN];           // elu(q)+1
static __device__ float g_kf [NROWS*HIDN];           // elu(k)+1
static __device__ float g_vv [NROWS*HIDN];           // v
static __device__ float g_att[NROWS*HIDN];           // attention output (pre Wo)
static __device__ float g_A  [BB*NC*NH*CHK*CHK];     // masked intra-chunk scores
static __device__ float g_kv [BB*NH*NC*HD*HD];       // per-chunk KV outer -> exclusive scan
static __device__ float g_ks [BB*NH*NC*HD];          // per-chunk k-sums  -> exclusive scan
static __device__ float g_z  [NROWS*NH];             // z_intra (then read by 4b)

// ============================================================================
// TF32x3 tensor-core GEMM (error-compensated: D += Ah*Bh + Ah*Bl + Al*Bh).
// 128x128 CTA tile, 256 threads = 8 warps (2x4), warp tile 64x32,
// m16n8k8 mma fragments, BK=16, split-to-tf32 hoisted into smem fill.
// ============================================================================

__device__ __forceinline__ uint32_t f2tf32(float x) {
    uint32_t r; asm("cvt.rna.tf32.f32 %0, %1;" : "=r"(r) : "f"(x)); return r;
}

__device__ __forceinline__ void mma_tf32(
    float& c0, float& c1, float& c2, float& c3,
    uint32_t a0, uint32_t a1, uint32_t a2, uint32_t a3,
    uint32_t b0, uint32_t b1)
{
    asm volatile(
        "mma.sync.aligned.m16n8k8.row.col.f32.tf32.tf32.f32 "
        "{%0,%1,%2,%3}, {%4,%5,%6,%7}, {%8,%9}, {%0,%1,%2,%3};"
        : "+f"(c0), "+f"(c1), "+f"(c2), "+f"(c3)
        : "r"(a0), "r"(a1), "r"(a2), "r"(a3), "r"(b0), "r"(b1));
}

// C[128,128] tile at (m0,n0):  C = A[m0:,:K] * B[:K, n0:]  (both row-major)
// Epilogue: v = acc + bias[col]; if ACT: v = elu(v)+1; store to Out.
template <int ACT>
__device__ __forceinline__ void gemm_tf32_tile(
    const float* __restrict__ Ap, long lda,
    const float* __restrict__ Bp, long ldb,
    int K, const float* __restrict__ bias,
    float* __restrict__ Out, long ldo,
    long m0, long n0)
{
    __shared__ float Ah[128][17], Al[128][17];   // [m][k], pad 17
    __shared__ float Bh[16][132], Bl[16][132];   // [k][n], pad 132

    const int tid  = threadIdx.x;
    const int wid  = tid >> 5;
    const int lane = tid & 31;
    const int g    = lane >> 2;        // group id 0..7
    const int tig  = lane & 3;         // thread-in-group 0..3
    const int wm0  = (wid >> 2) * 64;  // warp row offset (0 or 64)
    const int wn0  = (wid & 3) * 32;   // warp col offset (0,32,64,96)

    float c[4][4][4];                   // [mf][nf][4]
    #pragma unroll
    for (int i = 0; i < 4; i++)
        #pragma unroll
        for (int j = 0; j < 4; j++)
            #pragma unroll
            for (int r = 0; r < 4; r++) c[i][j][r] = 0.0f;

    const float* Abase = Ap + m0 * lda;
    const float* Bbase = Bp + n0;

    for (int kt = 0; kt < K; kt += 16) {
        __syncthreads();
        // ---- load + split A tile: 128 rows x 16 k  (512 float4, 2/thread)
        #pragma unroll
        for (int it = 0; it < 2; it++) {
            int lin = tid + it * 256;          // 0..511
            int r   = lin >> 2;                // m 0..127
            int c4  = (lin & 3) * 4;           // k 0,4,8,12
            float4 v = *(const float4*)(Abase + (long)r * lda + kt + c4);
            float vv[4] = {v.x, v.y, v.z, v.w};
            #pragma unroll
            for (int q = 0; q < 4; q++) {
                uint32_t hi = f2tf32(vv[q]);
                float    hf = __uint_as_float(hi);
                uint32_t lo = f2tf32(vv[q] - hf);
                Ah[r][c4 + q] = hf;
                Al[r][c4 + q] = __uint_as_float(lo);
            }
        }
        // ---- load + split B tile: 16 k x 128 n
        #pragma unroll
        for (int it = 0; it < 2; it++) {
            int lin = tid + it * 256;
            int r   = lin >> 5;                // k 0..15
            int c4  = (lin & 31) * 4;          // n
            float4 v = *(const float4*)(Bbase + (long)(kt + r) * ldb + c4);
            float vv[4] = {v.x, v.y, v.z, v.w};
            #pragma unroll
            for (int q = 0; q < 4; q++) {
                uint32_t hi = f2tf32(vv[q]);
                float    hf = __uint_as_float(hi);
                uint32_t lo = f2tf32(vv[q] - hf);
                Bh[r][c4 + q] = hf;
                Bl[r][c4 + q] = __uint_as_float(lo);
            }
        }
        __syncthreads();

        #pragma unroll
        for (int ks = 0; ks < 16; ks += 8) {
            uint32_t ah[4][4], al_[4][4];      // [mf][reg]
            #pragma unroll
            for (int mf = 0; mf < 4; mf++) {
                int m = wm0 + mf * 16;
                ah[mf][0]  = __float_as_uint(Ah[m + g    ][ks + tig    ]);
                ah[mf][1]  = __float_as_uint(Ah[m + g + 8][ks + tig    ]);
                ah[mf][2]  = __float_as_uint(Ah[m + g    ][ks + tig + 4]);
                ah[mf][3]  = __float_as_uint(Ah[m + g + 8][ks + tig + 4]);
                al_[mf][0] = __float_as_uint(Al[m + g    ][ks + tig    ]);
                al_[mf][1] = __float_as_uint(Al[m + g + 8][ks + tig    ]);
                al_[mf][2] = __float_as_uint(Al[m + g    ][ks + tig + 4]);
                al_[mf][3] = __float_as_uint(Al[m + g + 8][ks + tig + 4]);
            }
            uint32_t bh[4][2], bl_[4][2];      // [nf][reg]
            #pragma unroll
            for (int nf = 0; nf < 4; nf++) {
                int n = wn0 + nf * 8;
                bh[nf][0]  = __float_as_uint(Bh[ks + tig    ][n + g]);
                bh[nf][1]  = __float_as_uint(Bh[ks + tig + 4][n + g]);
                bl_[nf][0] = __float_as_uint(Bl[ks + tig    ][n + g]);
                bl_[nf][1] = __float_as_uint(Bl[ks + tig + 4][n + g]);
            }
            #pragma unroll
            for (int mf = 0; mf < 4; mf++)
                #pragma unroll
                for (int nf = 0; nf < 4; nf++) {
                    float* cc = c[mf][nf];
                    mma_tf32(cc[0], cc[1], cc[2], cc[3],
                             ah[mf][0], ah[mf][1], ah[mf][2], ah[mf][3],
                             bh[nf][0], bh[nf][1]);
                    mma_tf32(cc[0], cc[1], cc[2], cc[3],
                             ah[mf][0], ah[mf][1], ah[mf][2], ah[mf][3],
                             bl_[nf][0], bl_[nf][1]);
                    mma_tf32(cc[0], cc[1], cc[2], cc[3],
                             al_[mf][0], al_[mf][1], al_[mf][2], al_[mf][3],
                             bh[nf][0], bh[nf][1]);
                }
        }
    }

    // ---- epilogue: bias (+ optional elu+1), float2 stores
    #pragma unroll
    for (int mf = 0; mf < 4; mf++) {
        #pragma unroll
        for (int nf = 0; nf < 4; nf++) {
            long colg = n0 + wn0 + nf * 8 + tig * 2;
            float b0 = bias[colg], b1 = bias[colg + 1];
            #pragma unroll
            for (int half = 0; half < 2; half++) {
                long rowg = m0 + wm0 + mf * 16 + g + half * 8;
                float v0 = c[mf][nf][half * 2 + 0] + b0;
                float v1 = c[mf][nf][half * 2 + 1] + b1;
                if (ACT) {
                    v0 = (v0 > 0.0f) ? (v0 + 1.0f) : expf(v0);
                    v1 = (v1 > 0.0f) ? (v1 + 1.0f) : expf(v1);
                }
                *(float2*)(Out + rowg * ldo + colg) = make_float2(v0, v1);
            }
        }
    }
}

// ============================================================================
// Kernel 1: fused QKV projections + bias + feature map (elu+1 on q,k)
// grid = (HIDN/128, NROWS/128, 3)
// ============================================================================
__global__ void __launch_bounds__(256) proj_kernel(
    const float* __restrict__ X,
    const float* __restrict__ Wq, const float* __restrict__ bq,
    const float* __restrict__ Wk, const float* __restrict__ bk,
    const float* __restrict__ Wv, const float* __restrict__ bv)
{
    long m0 = (long)blockIdx.y * 128;
    long n0 = (long)blockIdx.x * 128;
    if (blockIdx.z == 0)
        gemm_tf32_tile<1>(X, HIDN, Wq, HIDN, HIDN, bq, g_qf, HIDN, m0, n0);
    else if (blockIdx.z == 1)
        gemm_tf32_tile<1>(X, HIDN, Wk, HIDN, HIDN, bk, g_kf, HIDN, m0, n0);
    else
        gemm_tf32_tile<0>(X, HIDN, Wv, HIDN, HIDN, bv, g_vv, HIDN, m0, n0);
}

// ============================================================================
// Kernel 5: output projection  out = att @ Wo + bo   (same tf32x3 core)
// ============================================================================
__global__ void __launch_bounds__(256) outproj_kernel(
    const float* __restrict__ Wo, const float* __restrict__ bo,
    float* __restrict__ out)
{
    long m0 = (long)blockIdx.y * 128;
    long n0 = (long)blockIdx.x * 128;
    gemm_tf32_tile<0>(g_att, HIDN, Wo, HIDN, HIDN, bo, out, HIDN, m0, n0);
}

// ============================================================================
// SIMT fp32 GEMM cores for the (small) attention-internal kernels.
// 128x128 block tile, 256 threads, 8x8 per thread, BK=16.
// ============================================================================
__device__ __forceinline__ void gemm_nn(
    const float* __restrict__ Ap, long lda,
    const float* __restrict__ Bp, long ldb,
    int K, float (&acc)[8][8])
{
    __shared__ float As[16][128];   // [kk][m]
    __shared__ float Bs[16][128];   // [kk][n]
    int tid = threadIdx.x;
    int tx = tid & 15, ty = tid >> 4;
    for (int kt = 0; kt < K; kt += 16) {
        __syncthreads();
        #pragma unroll
        for (int it = 0; it < 2; it++) {
            int lin = tid + it * 256;
            int r   = lin >> 2;
            int cq  = (lin & 3) * 4;
            float4 va = *(const float4*)(Ap + (long)r * lda + kt + cq);
            As[cq + 0][r] = va.x; As[cq + 1][r] = va.y;
            As[cq + 2][r] = va.z; As[cq + 3][r] = va.w;
        }
        #pragma unroll
        for (int it = 0; it < 2; it++) {
            int lin = tid + it * 256;
            int r   = lin >> 5;
            int c4  = (lin & 31) * 4;
            *(float4*)&Bs[r][c4] = *(const float4*)(Bp + (long)(kt + r) * ldb + c4);
        }
        __syncthreads();
        #pragma unroll
        for (int kk = 0; kk < 16; kk++) {
            float a[8], b[8];
            *(float4*)&a[0] = *(float4*)&As[kk][ty * 8];
            *(float4*)&a[4] = *(float4*)&As[kk][ty * 8 + 4];
            *(float4*)&b[0] = *(float4*)&Bs[kk][tx * 8];
            *(float4*)&b[4] = *(float4*)&Bs[kk][tx * 8 + 4];
            #pragma unroll
            for (int i = 0; i < 8; i++)
                #pragma unroll
                for (int j = 0; j < 8; j++)
                    acc[i][j] += a[i] * b[j];
        }
    }
    __syncthreads();
}

// out[c,k] = sum_d A[c,d] * B[k,d]  (both K-major rows)
__device__ __forceinline__ void gemm_nt(
    const float* __restrict__ Ap, long lda,
    const float* __restrict__ Bp, long ldb,
    int K, float (&acc)[8][8])
{
    __shared__ float As[16][128];
    __shared__ float Bs[16][128];
    int tid = threadIdx.x;
    int tx = tid & 15, ty = tid >> 4;
    for (int kt = 0; kt < K; kt += 16) {
        __syncthreads();
        #pragma unroll
        for (int it = 0; it < 2; it++) {
            int lin = tid + it * 256;
            int r   = lin >> 2;
            int cq  = (lin & 3) * 4;
            float4 va = *(const float4*)(Ap + (long)r * lda + kt + cq);
            As[cq + 0][r] = va.x; As[cq + 1][r] = va.y;
            As[cq + 2][r] = va.z; As[cq + 3][r] = va.w;
            float4 vb = *(const float4*)(Bp + (long)r * ldb + kt + cq);
            Bs[cq + 0][r] = vb.x; Bs[cq + 1][r] = vb.y;
            Bs[cq + 2][r] = vb.z; Bs[cq + 3][r] = vb.w;
        }
        __syncthreads();
        #pragma unroll
        for (int kk = 0; kk < 16; kk++) {
            float a[8], b[8];
            *(float4*)&a[0] = *(float4*)&As[kk][ty * 8];
            *(float4*)&a[4] = *(float4*)&As[kk][ty * 8 + 4];
            *(float4*)&b[0] = *(float4*)&Bs[kk][tx * 8];
            *(float4*)&b[4] = *(float4*)&Bs[kk][tx * 8 + 4];
            #pragma unroll
            for (int i = 0; i < 8; i++)
                #pragma unroll
                for (int j = 0; j < 8; j++)
                    acc[i][j] += a[i] * b[j];
        }
    }
    __syncthreads();
}

// ============================================================================
// Kernel 2: per-chunk KV outer product + k-sum.
// ============================================================================
__global__ void __launch_bounds__(256) chunk_kv_kernel()
{
    int bx = blockIdx.x;
    int h = bx % NH, n = (bx / NH) % NC, b = bx / (NH * NC);
    const float* kf = g_kf + ((long)(b * SEQ + n * CHK)) * HIDN + h * HD;
    const float* vv = g_vv + ((long)(b * SEQ + n * CHK)) * HIDN + h * HD;

    __shared__ float Ks[16][128];
    __shared__ float Vs[16][128];
    int tid = threadIdx.x, tx = tid & 15, ty = tid >> 4;
    float acc[8][8] = {};
    float ks = 0.0f;

    for (int ct = 0; ct < CHK; ct += 16) {
        __syncthreads();
        #pragma unroll
        for (int it = 0; it < 2; it++) {
            int lin = tid + it * 256;
            int r = lin >> 5, c4 = (lin & 31) * 4;
            *(float4*)&Ks[r][c4] = *(const float4*)(kf + (long)(ct + r) * HIDN + c4);
            *(float4*)&Vs[r][c4] = *(const float4*)(vv + (long)(ct + r) * HIDN + c4);
        }
        __syncthreads();
        if (tid < 128) {
            #pragma unroll
            for (int cc = 0; cc < 16; cc++) ks += Ks[cc][tid];
        }
        #pragma unroll
        for (int cc = 0; cc < 16; cc++) {
            float a[8], bv_[8];
            *(float4*)&a[0]   = *(float4*)&Ks[cc][ty * 8];
            *(float4*)&a[4]   = *(float4*)&Ks[cc][ty * 8 + 4];
            *(float4*)&bv_[0] = *(float4*)&Vs[cc][tx * 8];
            *(float4*)&bv_[4] = *(float4*)&Vs[cc][tx * 8 + 4];
            #pragma unroll
            for (int i = 0; i < 8; i++)
                #pragma unroll
                for (int j = 0; j < 8; j++)
                    acc[i][j] += a[i] * bv_[j];
        }
    }

    long obase = ((long)(b * NH + h) * NC + n) * (HD * HD);
    #pragma unroll
    for (int i = 0; i < 8; i++)
        #pragma unroll
        for (int j = 0; j < 8; j++)
            g_kv[obase + (long)(ty * 8 + i) * HD + tx * 8 + j] = acc[i][j];
    if (tid < 128)
        g_ks[((long)(b * NH + h) * NC + n) * HD + tid] = ks;
}

// ============================================================================
// Kernel 3: exclusive prefix scan over chunk axis (in place). Deterministic.
// ============================================================================
__global__ void scan_kv_kernel()
{
    long lane = (long)blockIdx.x * 256 + threadIdx.x;
    long bh  = lane / (HD * HD);
    long off = lane % (HD * HD);
    long base = bh * NC * (HD * HD) + off;
    float run = 0.0f;
    #pragma unroll
    for (int n = 0; n < NC; n++) {
        long idx = base + (long)n * (HD * HD);
        float t = g_kv[idx];
        g_kv[idx] = run;
        run += t;
    }
}

__global__ void scan_ks_kernel()
{
    int lane = blockIdx.x * 256 + threadIdx.x;
    int bh  = lane / HD;
    int off = lane % HD;
    long base = (long)bh * NC * HD + off;
    float run = 0.0f;
    #pragma unroll
    for (int n = 0; n < NC; n++) {
        long idx = base + (long)n * HD;
        float t = g_ks[idx];
        g_ks[idx] = run;
        run += t;
    }
}

// ============================================================================
// Kernel 4a: intra-chunk scores A = mask(qf @ kf^T), row sums -> g_z.
// ============================================================================
__global__ void __launch_bounds__(256) chunk_A_kernel()
{
    int bx = blockIdx.x;
    int h = bx % NH, n = (bx / NH) % NC, b = bx / (NH * NC);
    const float* qf = g_qf + ((long)(b * SEQ + n * CHK)) * HIDN + h * HD;
    const float* kf = g_kf + ((long)(b * SEQ + n * CHK)) * HIDN + h * HD;

    float acc[8][8] = {};
    gemm_nt(qf, HIDN, kf, HIDN, HD, acc);

    __shared__ float zpart[16][128];
    int tid = threadIdx.x, tx = tid & 15, ty = tid >> 4;
    float* Aout = g_A + (long)bx * (CHK * CHK);
    #pragma unroll
    for (int i = 0; i < 8; i++) {
        int c = ty * 8 + i;
        float rs = 0.0f;
        #pragma unroll
        for (int j = 0; j < 8; j++) {
            int k = tx * 8 + j;
            float v = (k <= c) ? acc[i][j] : 0.0f;
            rs += v;
            Aout[(long)c * CHK + k] = v;
        }
        zpart[tx][c] = rs;    // deterministic reduction (no FP atomics)
    }
    __syncthreads();
    if (tid < 128) {
        float s = 0.0f;
        #pragma unroll
        for (int t = 0; t < 16; t++) s += zpart[t][tid];
        g_z[((long)(b * SEQ + n * CHK + tid)) * NH + h] = s;
    }
}

// ============================================================================
// Kernel 4b: out = (A @ v + qf @ S_ex) / (z_intra + qf . ks_ex + eps)
// ============================================================================
__global__ void __launch_bounds__(256) chunk_out_kernel()
{
    int bx = blockIdx.x;
    int h = bx % NH, n = (bx / NH) % NC, b = bx / (NH * NC);
    long cbase = ((long)(b * SEQ + n * CHK)) * HIDN + h * HD;
    const float* Ach = g_A  + (long)bx * (CHK * CHK);
    const float* vv  = g_vv + cbase;
    const float* qf  = g_qf + cbase;
    const float* Sst = g_kv + ((long)(b * NH + h) * NC + n) * (HD * HD);
    const float* ksx = g_ks + ((long)(b * NH + h) * NC + n) * HD;

    float acc[8][8] = {};
    gemm_nn(Ach, CHK, vv, HIDN, CHK, acc);   // intra:  A @ v
    gemm_nn(qf, HIDN, Sst, HD, HD, acc);     // inter: qf @ S_exclusive

    __shared__ float ksm[128];
    __shared__ float zden[128];
    int tid = threadIdx.x, tx = tid & 15, ty = tid >> 4;
    if (tid < 128) ksm[tid] = ksx[tid];
    __syncthreads();
    if (tid < 128) {
        const float* qrow = qf + (long)tid * HIDN;
        float zi = 0.0f;
        #pragma unroll 8
        for (int d = 0; d < HD; d++) zi += qrow[d] * ksm[d];
        zden[tid] = zi + g_z[((long)(b * SEQ + n * CHK + tid)) * NH + h] + FEPS;
    }
    __syncthreads();

    float* outp = g_att + cbase;
    #pragma unroll
    for (int i = 0; i < 8; i++) {
        float inv = 1.0f / zden[ty * 8 + i];
        #pragma unroll
        for (int j = 0; j < 8; j++)
            outp[(long)(ty * 8 + i) * HIDN + tx * 8 + j] = acc[i][j] * inv;
    }
}

// ============================================================================
extern "C" void kernel_launch(void* const* d_in, const int* in_sizes, int n_in,
                              void* d_out, int out_size)
{
    (void)in_sizes; (void)n_in; (void)out_size;
    const float* x  = (const float*)d_in[0];
    const float* Wq = (const float*)d_in[1];
    const float* bq = (const float*)d_in[2];
    const float* Wk = (const float*)d_in[3];
    const float* bk = (const float*)d_in[4];
    const float* Wv = (const float*)d_in[5];
    const float* bv = (const float*)d_in[6];
    const float* Wo = (const float*)d_in[7];
    const float* bo = (const float*)d_in[8];
    float* out = (float*)d_out;

    dim3 gproj(HIDN / 128, NROWS / 128, 3);          // 16 x 64 x 3
    proj_kernel<<<gproj, 256>>>(x, Wq, bq, Wk, bk, Wv, bv);

    chunk_kv_kernel<<<BB * NC * NH, 256>>>();        // 1024 blocks
    scan_kv_kernel<<<(BB * NH * HD * HD) / 256, 256>>>();
    scan_ks_kernel<<<(BB * NH * HD) / 256, 256>>>();
    chunk_A_kernel<<<BB * NC * NH, 256>>>();
    chunk_out_kernel<<<BB * NC * NH, 256>>>();

    dim3 gout(HIDN / 128, NROWS / 128);              // 16 x 64
    outproj_kernel<<<gout, 256>>>(Wo, bo, out);
}

// round 9
// speedup vs baseline: 1.3111x; 1.3111x over previous
#include <cuda_runtime.h>
#include <math.h>
#include <stdint.h>

// Problem constants
#define BB    2
#define SEQ   4096
#define NH    16
#define HD    128
#define HIDN  2048
#define CHK   128
#define NC    32
#define NROWS (BB*SEQ)      // 8192
#define FEPS  1e-6f

#define KN2   (HIDN*HIDN*2)      // interleaved hi/lo W matrix size (floats)

// ---------------- scratch (device globals; no runtime allocation allowed) ----
static __device__ float g_qf [NROWS*HIDN];           // elu(q)+1
static __device__ float g_kf [NROWS*HIDN];           // elu(k)+1
static __device__ float g_vv [NROWS*HIDN];           // v
static __device__ float g_A  [BB*NC*NH*CHK*CHK];     // masked intra-chunk scores
static __device__ float g_kv [BB*NH*NC*HD*HD];       // per-chunk KV outer -> exclusive scan
static __device__ float g_ks [BB*NH*NC*HD];          // per-chunk k-sums  -> exclusive scan
static __device__ float g_z  [NROWS*NH];             // z_intra (then read by 4b)
// pre-split tf32 hi/lo operands
static __device__ float g_xh  [NROWS*HIDN];          // X hi
static __device__ float g_xl  [NROWS*HIDN];          // X lo
static __device__ float g_whl [3*KN2];               // Wq|Wk|Wv interleaved [k][n][2]
static __device__ float g_wohl[KN2];                 // Wo interleaved
static __device__ float g_atth[NROWS*HIDN];          // attention out hi
static __device__ float g_attl[NROWS*HIDN];          // attention out lo

// ============================================================================
// Helpers
// ============================================================================
__device__ __forceinline__ uint32_t f2tf32(float x) {
    uint32_t r; asm("cvt.rna.tf32.f32 %0, %1;" : "=r"(r) : "f"(x)); return r;
}

__device__ __forceinline__ void mma_tf32(
    float& c0, float& c1, float& c2, float& c3,
    uint32_t a0, uint32_t a1, uint32_t a2, uint32_t a3,
    uint32_t b0, uint32_t b1)
{
    asm volatile(
        "mma.sync.aligned.m16n8k8.row.col.f32.tf32.tf32.f32 "
        "{%0,%1,%2,%3}, {%4,%5,%6,%7}, {%8,%9}, {%0,%1,%2,%3};"
        : "+f"(c0), "+f"(c1), "+f"(c2), "+f"(c3)
        : "r"(a0), "r"(a1), "r"(a2), "r"(a3), "r"(b0), "r"(b1));
}

__device__ __forceinline__ void mma4(float* cc, const uint32_t* a, uint32_t b0, uint32_t b1) {
    mma_tf32(cc[0], cc[1], cc[2], cc[3], a[0], a[1], a[2], a[3], b0, b1);
}

__device__ __forceinline__ void ldsm4(uint32_t* r, uint32_t addr) {
    asm volatile("ldmatrix.sync.aligned.m8n8.x4.shared.b16 {%0,%1,%2,%3}, [%4];"
        : "=r"(r[0]), "=r"(r[1]), "=r"(r[2]), "=r"(r[3]) : "r"(addr));
}

__device__ __forceinline__ void cpa16(uint32_t dst, const void* src) {
    asm volatile("cp.async.cg.shared.global [%0], [%1], 16;" :: "r"(dst), "l"(src));
}
__device__ __forceinline__ void cp_commit() {
    asm volatile("cp.async.commit_group;");
}
template <int N>
__device__ __forceinline__ void cp_wait() {
    asm volatile("cp.async.wait_group %0;" :: "n"(N));
}

// ============================================================================
// Pre-split kernels (tf32 hi/lo decomposition, hoisted out of the GEMM)
// ============================================================================
__global__ void split_pair_kernel(const float* __restrict__ s,
                                  float* __restrict__ h, float* __restrict__ l, long n)
{
    for (long i = (long)blockIdx.x * blockDim.x + threadIdx.x; i < n;
         i += (long)gridDim.x * blockDim.x) {
        float v = s[i];
        uint32_t hb = f2tf32(v);
        float hf = __uint_as_float(hb);
        h[i] = hf;
        l[i] = __uint_as_float(f2tf32(v - hf));
    }
}

__global__ void split_ilv_kernel(const float* __restrict__ s, float* __restrict__ d2, long n)
{
    for (long i = (long)blockIdx.x * blockDim.x + threadIdx.x; i < n;
         i += (long)gridDim.x * blockDim.x) {
        float v = s[i];
        uint32_t hb = f2tf32(v);
        float hf = __uint_as_float(hb);
        d2[2 * i]     = hf;
        d2[2 * i + 1] = __uint_as_float(f2tf32(v - hf));
    }
}

// ============================================================================
// TF32x3 GEMM v2.1: pre-split operands, cp.async double buffer, ldmatrix frags.
// 128x128 CTA tile, 256 thr = 8 warps (2x4), warp tile 64x32, BK=16.
// smem stage (floats): Ah[128][20] @0, Al[128][20] @2560, Bhl[16][260] @5120.
// B row padded to 260 floats (+4 words) so the 4 tig-rows of a fragment hit
// disjoint bank groups (row stride no longer 0 mod 32 banks).
// Stage = 9280 floats (37,120B); two stages = 74,240B dynamic smem.
// ============================================================================
#define BROW    260
#define STG_F   9280
#define AL_OFF  2560
#define B_OFF   5120
#define SMEM_BYTES (2*STG_F*4)

__device__ __forceinline__ void fill_stage(
    uint32_t sb,                       // smem u32 addr of stage base
    const float* __restrict__ Ah_g, const float* __restrict__ Al_g, long lda,
    const float* __restrict__ Bhl_g, long ldb2,
    long m0, long n0, int kt, int tid)
{
    #pragma unroll
    for (int i = 0; i < 2; i++) {                  // A hi/lo: 128 rows x 64B each
        int cidx = tid + i * 256;
        int r = cidx >> 2, sg = (cidx & 3) * 4;
        uint32_t d = sb + (uint32_t)(r * 20 + sg) * 4u;
        cpa16(d, Ah_g + (m0 + r) * lda + kt + sg);
        cpa16(d + AL_OFF * 4u, Al_g + (m0 + r) * lda + kt + sg);
    }
    #pragma unroll
    for (int i = 0; i < 4; i++) {                  // Bhl: 16 rows x 1KB data
        int cidx = tid + i * 256;
        int r = cidx >> 6, of = (cidx & 63) * 4;
        cpa16(sb + (uint32_t)(B_OFF + r * BROW + of) * 4u,
              Bhl_g + (long)(kt + r) * ldb2 + n0 * 2 + of);
    }
}

// Epilogue: v = acc + bias[col]; ACT => elu(v)+1.
template <int ACT>
__device__ __forceinline__ void gemm2_core(
    const float* __restrict__ Ah_g, const float* __restrict__ Al_g, long lda,
    const float* __restrict__ Bhl_g, long ldb2, int K,
    const float* __restrict__ bias,
    float* __restrict__ Out, long ldo,
    long m0, long n0)
{
    extern __shared__ float smem[];
    const int tid  = threadIdx.x;
    const int wid  = tid >> 5;
    const int lane = tid & 31;
    const int g    = lane >> 2;
    const int tig  = lane & 3;
    const int wm0  = (wid >> 2) * 64;
    const int wn0  = (wid & 3) * 32;
    // ldmatrix per-lane row/col-offset (maps the 4 8x4-b32 tiles of an m16k8 frag)
    const int arow = ((lane >> 3) & 1) * 8 + (lane & 7);
    const int akc  = (lane >> 4) * 4;
    const uint32_t sbase = (uint32_t)__cvta_generic_to_shared(smem);

    float c[4][4][4];
    #pragma unroll
    for (int i = 0; i < 4; i++)
        #pragma unroll
        for (int j = 0; j < 4; j++)
            #pragma unroll
            for (int r = 0; r < 4; r++) c[i][j][r] = 0.0f;

    const int NT = K / 16;
    fill_stage(sbase, Ah_g, Al_g, lda, Bhl_g, ldb2, m0, n0, 0, tid);
    cp_commit();

    for (int t = 0; t < NT; t++) {
        if (t + 1 < NT) {
            fill_stage(sbase + (uint32_t)(((t + 1) & 1) * STG_F) * 4u,
                       Ah_g, Al_g, lda, Bhl_g, ldb2, m0, n0, (t + 1) * 16, tid);
            cp_commit();
            cp_wait<1>();
        } else {
            cp_wait<0>();
        }
        __syncthreads();

        const int so = (t & 1) * STG_F;
        const uint32_t sa = sbase + (uint32_t)so * 4u;
        #pragma unroll
        for (int ks = 0; ks < 16; ks += 8) {
            uint32_t ah[4][4], al[4][4];
            #pragma unroll
            for (int mf = 0; mf < 4; mf++) {
                uint32_t adr = sa + (uint32_t)((wm0 + mf * 16 + arow) * 20 + ks + akc) * 4u;
                ldsm4(ah[mf], adr);
                ldsm4(al[mf], adr + AL_OFF * 4u);
            }
            #pragma unroll
            for (int nf = 0; nf < 4; nf++) {
                int n2 = (wn0 + nf * 8 + g) * 2;
                float2 p0 = *(const float2*)&smem[so + B_OFF + (ks + tig)     * BROW + n2];
                float2 p1 = *(const float2*)&smem[so + B_OFF + (ks + tig + 4) * BROW + n2];
                uint32_t bh0 = __float_as_uint(p0.x), bl0 = __float_as_uint(p0.y);
                uint32_t bh1 = __float_as_uint(p1.x), bl1 = __float_as_uint(p1.y);
                #pragma unroll
                for (int mf = 0; mf < 4; mf++) {
                    mma4(c[mf][nf], ah[mf], bh0, bh1);   // Ah*Bh
                    mma4(c[mf][nf], ah[mf], bl0, bl1);   // Ah*Bl
                    mma4(c[mf][nf], al[mf], bh0, bh1);   // Al*Bh
                }
            }
        }
        __syncthreads();
    }

    // ---- epilogue
    #pragma unroll
    for (int mf = 0; mf < 4; mf++) {
        #pragma unroll
        for (int nf = 0; nf < 4; nf++) {
            long colg = n0 + wn0 + nf * 8 + tig * 2;
            float b0 = __ldg(bias + colg), b1 = __ldg(bias + colg + 1);
            #pragma unroll
            for (int half = 0; half < 2; half++) {
                long rowg = m0 + wm0 + mf * 16 + g + half * 8;
                float v0 = c[mf][nf][half * 2 + 0] + b0;
                float v1 = c[mf][nf][half * 2 + 1] + b1;
                if (ACT) {
                    v0 = (v0 > 0.0f) ? (v0 + 1.0f) : expf(v0);
                    v1 = (v1 > 0.0f) ? (v1 + 1.0f) : expf(v1);
                }
                *(float2*)(Out + rowg * ldo + colg) = make_float2(v0, v1);
            }
        }
    }
}

__global__ void __launch_bounds__(256, 2) proj2_kernel(
    const float* __restrict__ bq, const float* __restrict__ bk,
    const float* __restrict__ bv)
{
    long m0 = (long)blockIdx.y * 128;
    long n0 = (long)blockIdx.x * 128;
    int z = blockIdx.z;
    if (z == 0)
        gemm2_core<1>(g_xh, g_xl, HIDN, g_whl,           2 * HIDN, HIDN, bq, g_qf, HIDN, m0, n0);
    else if (z == 1)
        gemm2_core<1>(g_xh, g_xl, HIDN, g_whl + KN2,     2 * HIDN, HIDN, bk, g_kf, HIDN, m0, n0);
    else
        gemm2_core<0>(g_xh, g_xl, HIDN, g_whl + 2 * KN2, 2 * HIDN, HIDN, bv, g_vv, HIDN, m0, n0);
}

__global__ void __launch_bounds__(256, 2) outproj2_kernel(
    const float* __restrict__ bo, float* __restrict__ out)
{
    long m0 = (long)blockIdx.y * 128;
    long n0 = (long)blockIdx.x * 128;
    gemm2_core<0>(g_atth, g_attl, HIDN, g_wohl, 2 * HIDN, HIDN, bo, out, HIDN, m0, n0);
}

// ============================================================================
// SIMT fp32 GEMM cores for attention-internal kernels (unchanged, proven).
// ============================================================================
__device__ __forceinline__ void gemm_nn(
    const float* __restrict__ Ap, long lda,
    const float* __restrict__ Bp, long ldb,
    int K, float (&acc)[8][8])
{
    __shared__ float As[16][128];
    __shared__ float Bs[16][128];
    int tid = threadIdx.x;
    int tx = tid & 15, ty = tid >> 4;
    for (int kt = 0; kt < K; kt += 16) {
        __syncthreads();
        #pragma unroll
        for (int it = 0; it < 2; it++) {
            int lin = tid + it * 256;
            int r   = lin >> 2;
            int cq  = (lin & 3) * 4;
            float4 va = *(const float4*)(Ap + (long)r * lda + kt + cq);
            As[cq + 0][r] = va.x; As[cq + 1][r] = va.y;
            As[cq + 2][r] = va.z; As[cq + 3][r] = va.w;
        }
        #pragma unroll
        for (int it = 0; it < 2; it++) {
            int lin = tid + it * 256;
            int r   = lin >> 5;
            int c4  = (lin & 31) * 4;
            *(float4*)&Bs[r][c4] = *(const float4*)(Bp + (long)(kt + r) * ldb + c4);
        }
        __syncthreads();
        #pragma unroll
        for (int kk = 0; kk < 16; kk++) {
            float a[8], b[8];
            *(float4*)&a[0] = *(float4*)&As[kk][ty * 8];
            *(float4*)&a[4] = *(float4*)&As[kk][ty * 8 + 4];
            *(float4*)&b[0] = *(float4*)&Bs[kk][tx * 8];
            *(float4*)&b[4] = *(float4*)&Bs[kk][tx * 8 + 4];
            #pragma unroll
            for (int i = 0; i < 8; i++)
                #pragma unroll
                for (int j = 0; j < 8; j++)
                    acc[i][j] += a[i] * b[j];
        }
    }
    __syncthreads();
}

__device__ __forceinline__ void gemm_nt(
    const float* __restrict__ Ap, long lda,
    const float* __restrict__ Bp, long ldb,
    int K, float (&acc)[8][8])
{
    __shared__ float As[16][128];
    __shared__ float Bs[16][128];
    int tid = threadIdx.x;
    int tx = tid & 15, ty = tid >> 4;
    for (int kt = 0; kt < K; kt += 16) {
        __syncthreads();
        #pragma unroll
        for (int it = 0; it < 2; it++) {
            int lin = tid + it * 256;
            int r   = lin >> 2;
            int cq  = (lin & 3) * 4;
            float4 va = *(const float4*)(Ap + (long)r * lda + kt + cq);
            As[cq + 0][r] = va.x; As[cq + 1][r] = va.y;
            As[cq + 2][r] = va.z; As[cq + 3][r] = va.w;
            float4 vb = *(const float4*)(Bp + (long)r * ldb + kt + cq);
            Bs[cq + 0][r] = vb.x; Bs[cq + 1][r] = vb.y;
            Bs[cq + 2][r] = vb.z; Bs[cq + 3][r] = vb.w;
        }
        __syncthreads();
        #pragma unroll
        for (int kk = 0; kk < 16; kk++) {
            float a[8], b[8];
            *(float4*)&a[0] = *(float4*)&As[kk][ty * 8];
            *(float4*)&a[4] = *(float4*)&As[kk][ty * 8 + 4];
            *(float4*)&b[0] = *(float4*)&Bs[kk][tx * 8];
            *(float4*)&b[4] = *(float4*)&Bs[kk][tx * 8 + 4];
            #pragma unroll
            for (int i = 0; i < 8; i++)
                #pragma unroll
                for (int j = 0; j < 8; j++)
                    acc[i][j] += a[i] * b[j];
        }
    }
    __syncthreads();
}

// ============================================================================
// Kernel 2: per-chunk KV outer product + k-sum.
// ============================================================================
__global__ void __launch_bounds__(256) chunk_kv_kernel()
{
    int bx = blockIdx.x;
    int h = bx % NH, n = (bx / NH) % NC, b = bx / (NH * NC);
    const float* kf = g_kf + ((long)(b * SEQ + n * CHK)) * HIDN + h * HD;
    const float* vv = g_vv + ((long)(b * SEQ + n * CHK)) * HIDN + h * HD;

    __shared__ float Ks[16][128];
    __shared__ float Vs[16][128];
    int tid = threadIdx.x, tx = tid & 15, ty = tid >> 4;
    float acc[8][8] = {};
    float ks = 0.0f;

    for (int ct = 0; ct < CHK; ct += 16) {
        __syncthreads();
        #pragma unroll
        for (int it = 0; it < 2; it++) {
            int lin = tid + it * 256;
            int r = lin >> 5, c4 = (lin & 31) * 4;
            *(float4*)&Ks[r][c4] = *(const float4*)(kf + (long)(ct + r) * HIDN + c4);
            *(float4*)&Vs[r][c4] = *(const float4*)(vv + (long)(ct + r) * HIDN + c4);
        }
        __syncthreads();
        if (tid < 128) {
            #pragma unroll
            for (int cc = 0; cc < 16; cc++) ks += Ks[cc][tid];
        }
        #pragma unroll
        for (int cc = 0; cc < 16; cc++) {
            float a[8], bv_[8];
            *(float4*)&a[0]   = *(float4*)&Ks[cc][ty * 8];
            *(float4*)&a[4]   = *(float4*)&Ks[cc][ty * 8 + 4];
            *(float4*)&bv_[0] = *(float4*)&Vs[cc][tx * 8];
            *(float4*)&bv_[4] = *(float4*)&Vs[cc][tx * 8 + 4];
            #pragma unroll
            for (int i = 0; i < 8; i++)
                #pragma unroll
                for (int j = 0; j < 8; j++)
                    acc[i][j] += a[i] * bv_[j];
        }
    }

    long obase = ((long)(b * NH + h) * NC + n) * (HD * HD);
    #pragma unroll
    for (int i = 0; i < 8; i++)
        #pragma unroll
        for (int j = 0; j < 8; j++)
            g_kv[obase + (long)(ty * 8 + i) * HD + tx * 8 + j] = acc[i][j];
    if (tid < 128)
        g_ks[((long)(b * NH + h) * NC + n) * HD + tid] = ks;
}

// ============================================================================
// Kernel 3: exclusive prefix scan over chunk axis (in place). Deterministic.
// ============================================================================
__global__ void scan_kv_kernel()
{
    long lane = (long)blockIdx.x * 256 + threadIdx.x;
    long bh  = lane / (HD * HD);
    long off = lane % (HD * HD);
    long base = bh * NC * (HD * HD) + off;
    float run = 0.0f;
    #pragma unroll
    for (int n = 0; n < NC; n++) {
        long idx = base + (long)n * (HD * HD);
        float t = g_kv[idx];
        g_kv[idx] = run;
        run += t;
    }
}

__global__ void scan_ks_kernel()
{
    int lane = blockIdx.x * 256 + threadIdx.x;
    int bh  = lane / HD;
    int off = lane % HD;
    long base = (long)bh * NC * HD + off;
    float run = 0.0f;
    #pragma unroll
    for (int n = 0; n < NC; n++) {
        long idx = base + (long)n * HD;
        float t = g_ks[idx];
        g_ks[idx] = run;
        run += t;
    }
}

// ============================================================================
// Kernel 4a: intra-chunk scores A = mask(qf @ kf^T), row sums -> g_z.
// ============================================================================
__global__ void __launch_bounds__(256) chunk_A_kernel()
{
    int bx = blockIdx.x;
    int h = bx % NH, n = (bx / NH) % NC, b = bx / (NH * NC);
    const float* qf = g_qf + ((long)(b * SEQ + n * CHK)) * HIDN + h * HD;
    const float* kf = g_kf + ((long)(b * SEQ + n * CHK)) * HIDN + h * HD;

    float acc[8][8] = {};
    gemm_nt(qf, HIDN, kf, HIDN, HD, acc);

    __shared__ float zpart[16][128];
    int tid = threadIdx.x, tx = tid & 15, ty = tid >> 4;
    float* Aout = g_A + (long)bx * (CHK * CHK);
    #pragma unroll
    for (int i = 0; i < 8; i++) {
        int c = ty * 8 + i;
        float rs = 0.0f;
        #pragma unroll
        for (int j = 0; j < 8; j++) {
            int k = tx * 8 + j;
            float v = (k <= c) ? acc[i][j] : 0.0f;
            rs += v;
            Aout[(long)c * CHK + k] = v;
        }
        zpart[tx][c] = rs;    // deterministic reduction (no FP atomics)
    }
    __syncthreads();
    if (tid < 128) {
        float s = 0.0f;
        #pragma unroll
        for (int t = 0; t < 16; t++) s += zpart[t][tid];
        g_z[((long)(b * SEQ + n * CHK + tid)) * NH + h] = s;
    }
}

// ============================================================================
// Kernel 4b: out = (A @ v + qf @ S_ex) / (z_intra + qf . ks_ex + eps)
// Writes att pre-split into tf32 hi/lo for the outproj tensor GEMM.
// ============================================================================
__global__ void __launch_bounds__(256) chunk_out_kernel()
{
    int bx = blockIdx.x;
    int h = bx % NH, n = (bx / NH) % NC, b = bx / (NH * NC);
    long cbase = ((long)(b * SEQ + n * CHK)) * HIDN + h * HD;
    const float* Ach = g_A  + (long)bx * (CHK * CHK);
    const float* vv  = g_vv + cbase;
    const float* qf  = g_qf + cbase;
    const float* Sst = g_kv + ((long)(b * NH + h) * NC + n) * (HD * HD);
    const float* ksx = g_ks + ((long)(b * NH + h) * NC + n) * HD;

    float acc[8][8] = {};
    gemm_nn(Ach, CHK, vv, HIDN, CHK, acc);   // intra:  A @ v
    gemm_nn(qf, HIDN, Sst, HD, HD, acc);     // inter: qf @ S_exclusive

    __shared__ float ksm[128];
    __shared__ float zden[128];
    int tid = threadIdx.x, tx = tid & 15, ty = tid >> 4;
    if (tid < 128) ksm[tid] = ksx[tid];
    __syncthreads();
    if (tid < 128) {
        const float* qrow = qf + (long)tid * HIDN;
        float zi = 0.0f;
        #pragma unroll 8
        for (int d = 0; d < HD; d++) zi += qrow[d] * ksm[d];
        zden[tid] = zi + g_z[((long)(b * SEQ + n * CHK + tid)) * NH + h] + FEPS;
    }
    __syncthreads();

    #pragma unroll
    for (int i = 0; i < 8; i++) {
        float inv = 1.0f / zden[ty * 8 + i];
        #pragma unroll
        for (int j = 0; j < 8; j++) {
            long idx = cbase + (long)(ty * 8 + i) * HIDN + tx * 8 + j;
            float v = acc[i][j] * inv;
            uint32_t hb = f2tf32(v);
            float hf = __uint_as_float(hb);
            g_atth[idx] = hf;
            g_attl[idx] = __uint_as_float(f2tf32(v - hf));
        }
    }
}

// ============================================================================
extern "C" void kernel_launch(void* const* d_in, const int* in_sizes, int n_in,
                              void* d_out, int out_size)
{
    (void)in_sizes; (void)n_in; (void)out_size;
    const float* x  = (const float*)d_in[0];
    const float* Wq = (const float*)d_in[1];
    const float* bq = (const float*)d_in[2];
    const float* Wk = (const float*)d_in[3];
    const float* bk = (const float*)d_in[4];
    const float* Wv = (const float*)d_in[5];
    const float* bv = (const float*)d_in[6];
    const float* Wo = (const float*)d_in[7];
    const float* bo = (const float*)d_in[8];
    float* out = (float*)d_out;

    // opt into >48KB dynamic smem (idempotent, capture-safe host calls)
    cudaFuncSetAttribute(proj2_kernel,    cudaFuncAttributeMaxDynamicSharedMemorySize, SMEM_BYTES);
    cudaFuncSetAttribute(outproj2_kernel, cudaFuncAttributeMaxDynamicSharedMemorySize, SMEM_BYTES);

    // resolve device-global scratch addresses
    float *xh, *xl, *whl, *wohl;
    cudaGetSymbolAddress((void**)&xh,   g_xh);
    cudaGetSymbolAddress((void**)&xl,   g_xl);
    cudaGetSymbolAddress((void**)&whl,  g_whl);
    cudaGetSymbolAddress((void**)&wohl, g_wohl);

    // pre-split tf32 hi/lo
    split_pair_kernel<<<2048, 256>>>(x, xh, xl, (long)NROWS * HIDN);
    split_ilv_kernel<<<2048, 256>>>(Wq, whl,            (long)HIDN * HIDN);
    split_ilv_kernel<<<2048, 256>>>(Wk, whl + KN2,      (long)HIDN * HIDN);
    split_ilv_kernel<<<2048, 256>>>(Wv, whl + 2 * KN2,  (long)HIDN * HIDN);
    split_ilv_kernel<<<2048, 256>>>(Wo, wohl,           (long)HIDN * HIDN);

    dim3 gproj(HIDN / 128, NROWS / 128, 3);              // 16 x 64 x 3
    proj2_kernel<<<gproj, 256, SMEM_BYTES>>>(bq, bk, bv);

    chunk_kv_kernel<<<BB * NC * NH, 256>>>();            // 1024 blocks
    scan_kv_kernel<<<(BB * NH * HD * HD) / 256, 256>>>();
    scan_ks_kernel<<<(BB * NH * HD) / 256, 256>>>();
    chunk_A_kernel<<<BB * NC * NH, 256>>>();
    chunk_out_kernel<<<BB * NC * NH, 256>>>();

    dim3 gout(HIDN / 128, NROWS / 128);                  // 16 x 64
    outproj2_kernel<<<gout, 256, SMEM_BYTES>>>(bo, out);
}